// round 6
// baseline (speedup 1.0000x reference)
#include <cuda_runtime.h>
#include <cuda_bf16.h>
#include <cstdint>

// ===========================================================================
// HyperConvS: x NHWC bf16 hi/lo convert -> weight-gen -> implicit GEMM conv
// (mma.sync bf16x3, fp32 accum). M=256 x N=128 CTA, 512 threads.
// Stage = (32-ch chunk, tap-row of 3 taps): 24 stages, A and B both
// double-buffered, one barrier + full cp.async drain per stage.
// ===========================================================================

#define HH 64
#define WW 64
#define CC 256
#define OCC 256

__device__ __nv_bfloat16 g_xhi[32 * 64 * 64 * 256];   // NHWC
__device__ __nv_bfloat16 g_xlo[32 * 64 * 64 * 256];
__device__ __nv_bfloat16 g_whi[9 * 256 * 256];        // [tap][oc][ic]
__device__ __nv_bfloat16 g_wlo[9 * 256 * 256];

// ---- helpers ----
__device__ __forceinline__ uint32_t smem_u32(const void* p) {
    uint32_t a;
    asm("{ .reg .u64 t; cvta.to.shared.u64 t, %1; cvt.u32.u64 %0, t; }"
        : "=r"(a) : "l"(p));
    return a;
}
__device__ __forceinline__ void cp_async16(uint32_t dst, const void* src, uint32_t nbytes) {
    asm volatile("cp.async.cg.shared.global [%0], [%1], 16, %2;"
                 :: "r"(dst), "l"(src), "r"(nbytes) : "memory");
}
__device__ __forceinline__ void cp_commit() {
    asm volatile("cp.async.commit_group;" ::: "memory");
}
template <int N>
__device__ __forceinline__ void cp_wait() {
    asm volatile("cp.async.wait_group %0;" :: "n"(N) : "memory");
}
__device__ __forceinline__ void ldmx4(uint32_t* r, uint32_t addr) {
    asm volatile("ldmatrix.sync.aligned.m8n8.x4.shared.b16 {%0,%1,%2,%3}, [%4];"
                 : "=r"(r[0]), "=r"(r[1]), "=r"(r[2]), "=r"(r[3]) : "r"(addr));
}
__device__ __forceinline__ void mma16816(float* c, const uint32_t* a, const uint32_t* b) {
    asm volatile(
        "mma.sync.aligned.m16n8k16.row.col.f32.bf16.bf16.f32 "
        "{%0,%1,%2,%3}, {%4,%5,%6,%7}, {%8,%9}, {%0,%1,%2,%3};"
        : "+f"(c[0]), "+f"(c[1]), "+f"(c[2]), "+f"(c[3])
        : "r"(a[0]), "r"(a[1]), "r"(a[2]), "r"(a[3]), "r"(b[0]), "r"(b[1]));
}

// 64-byte-row swizzle: bank-group = (4r + (c ^ ((r>>1)&3))) mod 8 is distinct
// over any 8 consecutive rows -> conflict-free ldmatrix and stores.
#define SWC(c, r) ((uint32_t)((c) ^ (((r) >> 1) & 3)) << 4)

// ---------------------------------------------------------------------------
// Kernel: NCHW fp32 -> NHWC bf16 hi/lo transpose.
// ---------------------------------------------------------------------------
__global__ __launch_bounds__(256)
void x_convert_kernel(const float* __restrict__ x) {
    __shared__ float tile[128][68];
    const int y  = blockIdx.x;
    const int n  = blockIdx.y;
    const int cg = blockIdx.z;
    const int t  = threadIdx.x;

    {
        const int c_local = t >> 1;
        const int xh = (t & 1) * 32;
        const float4* src = (const float4*)(x +
            (((size_t)(n * CC + cg * 128 + c_local) * HH + y) * WW) + xh);
        #pragma unroll
        for (int k = 0; k < 8; ++k) {
            float4 v = src[k];
            tile[c_local][xh + k * 4 + 0] = v.x;
            tile[c_local][xh + k * 4 + 1] = v.y;
            tile[c_local][xh + k * 4 + 2] = v.z;
            tile[c_local][xh + k * 4 + 3] = v.w;
        }
    }
    __syncthreads();

    #pragma unroll
    for (int k = 0; k < 4; ++k) {
        const int q = t + 256 * k;
        const int xcol = q >> 4;
        const int cc = (q & 15) * 8;
        __align__(16) __nv_bfloat16 hv[8];
        __align__(16) __nv_bfloat16 lv[8];
        #pragma unroll
        for (int i = 0; i < 8; ++i) {
            float v = tile[cc + i][xcol];
            hv[i] = __float2bfloat16(v);
            lv[i] = __float2bfloat16(v - __bfloat162float(hv[i]));
        }
        const size_t dst = ((size_t)(n * HH + y) * WW + xcol) * 256 + cg * 128 + cc;
        *(uint4*)(g_xhi + dst) = *(const uint4*)hv;
        *(uint4*)(g_xlo + dst) = *(const uint4*)lv;
    }
}

// ---------------------------------------------------------------------------
// Kernel: weight generation (smem-transposed MLP weights).
// ---------------------------------------------------------------------------
__global__ __launch_bounds__(256)
void weight_gen_kernel(const float* __restrict__ z,
                       const float* __restrict__ W1,
                       const float* __restrict__ B1,
                       const float* __restrict__ W2,
                       const float* __restrict__ B2) {
    __shared__ float w1t[64 * 65];     // [n][d]
    __shared__ float w2t[64 * 149];    // [d][k]
    __shared__ float z_s[16 * 64];
    __shared__ float a_s[16 * 64];
    const int b  = blockIdx.x;
    const int lg = blockIdx.y;
    const int t  = threadIdx.x;

    for (int i = t; i < 64 * 64; i += 256) {
        const int d = i >> 6, n = i & 63;
        w1t[n * 65 + d] = W1[(b * 64 + d) * 64 + n];
    }
    for (int i = t; i < 144 * 64; i += 256) {
        const int k = i >> 6, d = i & 63;
        w2t[d * 149 + k] = W2[(b * 144 + k) * 64 + d];
    }
    for (int i = t; i < 1024; i += 256) z_s[i] = z[lg * 16 * 64 + i];
    __syncthreads();

    for (int i = t; i < 1024; i += 256) {
        const int il = i >> 6, d = i & 63;
        float s = B1[b * 64 + d];
        #pragma unroll 16
        for (int n = 0; n < 64; ++n) s += w1t[n * 65 + d] * z_s[il * 64 + n];
        a_s[i] = s;
    }
    __syncthreads();

    for (int i = t; i < 2304; i += 256) {
        const int il = i / 144, k = i - il * 144;
        float s = B2[b * 144 + k];
        #pragma unroll 16
        for (int d = 0; d < 64; ++d) s += w2t[d * 149 + k] * a_s[il * 64 + d];
        const int b2 = k / 9;
        const int tap = k - b2 * 9;
        const int o = lg * 16 + b2;
        const int ic = il * 16 + b;
        __nv_bfloat16 hi = __float2bfloat16(s);
        __nv_bfloat16 lo = __float2bfloat16(s - __bfloat162float(hi));
        g_whi[(tap * 256 + o) * 256 + ic] = hi;
        g_wlo[(tap * 256 + o) * 256 + ic] = lo;
    }
}

// ---------------------------------------------------------------------------
// Kernel: implicit-GEMM conv.
// CTA: 256 px (4 rows x 64 cols) x 128 oc, 512 threads / 16 warps
// (warp 32x64; warp_m = wid&7, warp_n = wid>>3).
// Stage s (0..23): chunk = s/3 (32 ch), tap-row = s%3 (dy fixed, dx -1..1).
// A: [2 buf][2 prec][396 halo rows][64 B], buffer = chunk&1, prefetch c+1 at
//    first stage of chunk c. B: [2 buf][3 dx][2 prec][128 oc][64 B],
//    buffer = s&1, prefetch s+1 each stage. One commit group per stage;
//    wait_group 0 + one __syncthreads at stage top.
// ---------------------------------------------------------------------------
#define A_PTILE 25344u                 // 396 * 64
#define A_BUF   (2 * A_PTILE)         // per buffer (2 prec)
#define A_REGION (2 * A_BUF)          // 101376
#define B_TILE  8192u                 // per (dx, prec)
#define B_STAGE (6 * B_TILE)          // 49152
#define B_OFF   A_REGION
#define SMEM_DYN (A_REGION + 2 * B_STAGE)   // 199680

struct Ctx {
    uint32_t sbase;
    int n, y0, oc0;
};

__device__ __forceinline__ void issue_A(const Ctx& c, int chunk, int t) {
    const int c0 = chunk * 32;
    const uint32_t bufo = (chunk & 1) ? A_BUF : 0u;
    #pragma unroll
    for (int it = 0; it < 2; ++it) {
        const int idx = t + it * 512;
        if (idx >= 792) break;
        const int pr = idx & 1;
        const int r = idx >> 1;                   // 0..395 halo row
        const int hrow = r / 66;
        const int hcol = r - hrow * 66;
        const int gy = c.y0 - 1 + hrow;
        const int gx = hcol - 1;
        const bool valid = ((unsigned)gy < 64u) && ((unsigned)gx < 64u);
        const __nv_bfloat16* xp = pr ? g_xlo : g_xhi;
        const __nv_bfloat16* src = valid
            ? xp + (((size_t)(c.n * HH + gy) * WW + gx) * 256 + c0)
            : xp;
        const uint32_t nb = valid ? 16u : 0u;
        const uint32_t dst = c.sbase + bufo + pr * A_PTILE + (uint32_t)r * 64;
        #pragma unroll
        for (int i = 0; i < 4; ++i)
            cp_async16(dst + SWC(i, r), src + i * 8, nb);
    }
}

__device__ __forceinline__ void issue_B(const Ctx& c, int s, int t) {
    const int chunk = s / 3;
    const int tr = s - chunk * 3;
    const uint32_t bufo = (uint32_t)(s & 1) * B_STAGE;
    #pragma unroll
    for (int it = 0; it < 3; ++it) {
        const int idx = t + it * 512;              // 0..1535
        const int rid = idx >> 1;
        const int half = idx & 1;
        const int dxi = rid >> 8;
        const int rem = rid & 255;
        const int pr = rem >> 7;
        const int oc = rem & 127;
        const int tap = tr * 3 + dxi;
        const __nv_bfloat16* wp = pr ? g_wlo : g_whi;
        const __nv_bfloat16* src =
            wp + ((size_t)(tap * 256 + c.oc0 + oc) * 256 + chunk * 32 + half * 16);
        const uint32_t dst = c.sbase + B_OFF + bufo
                           + (uint32_t)(dxi * 2 + pr) * B_TILE + (uint32_t)oc * 64;
        cp_async16(dst + SWC(half * 2 + 0, oc), src,     16u);
        cp_async16(dst + SWC(half * 2 + 1, oc), src + 8, 16u);
    }
}

__global__ __launch_bounds__(512, 1)
void conv_mma_kernel(float* __restrict__ out) {
    extern __shared__ char dsm[];
    const uint32_t sbase = smem_u32(dsm);

    const int t = threadIdx.x;
    const int lane = t & 31;
    const int wid = t >> 5;
    const int warp_m = wid & 7;
    const int warp_n = wid >> 3;
    const int y0 = blockIdx.x * 4;
    const int n = blockIdx.y;
    const int oc0 = blockIdx.z * 128;

    Ctx ctx; ctx.sbase = sbase; ctx.n = n; ctx.y0 = y0; ctx.oc0 = oc0;

    float acc[2][8][4];
    #pragma unroll
    for (int mi = 0; mi < 2; ++mi)
        #pragma unroll
        for (int ni = 0; ni < 8; ++ni)
            #pragma unroll
            for (int k = 0; k < 4; ++k) acc[mi][ni][k] = 0.f;

    const int la = lane & 15;
    const int ca = lane >> 4;
    const int lb = (lane & 7) + ((lane >> 4) << 3);
    const int cb = (lane >> 3) & 1;

    int arl[2], axc[2];
    #pragma unroll
    for (int mi = 0; mi < 2; ++mi) {
        const int m = warp_m * 32 + mi * 16 + la;   // 0..255
        arl[mi] = m >> 6;
        axc[mi] = m & 63;
    }

    // prologue: A(0) + B(0), one group
    issue_A(ctx, 0, t);
    issue_B(ctx, 0, t);
    cp_commit();

    for (int s = 0; s < 24; ++s) {
        cp_wait<0>();
        __syncthreads();

        // prefetch: A one chunk ahead (at chunk-first stage), B one stage ahead
        {
            bool did = false;
            if ((s % 3) == 0 && (s / 3) + 1 < 8) { issue_A(ctx, s / 3 + 1, t); did = true; }
            if (s + 1 < 24) { issue_B(ctx, s + 1, t); did = true; }
            if (did) cp_commit();
        }

        const int chunk = s / 3;
        const int dy = (s - chunk * 3) - 1;
        const uint32_t abase = sbase + ((chunk & 1) ? A_BUF : 0u);
        const uint32_t bstage = sbase + B_OFF + (uint32_t)(s & 1) * B_STAGE;

        #pragma unroll
        for (int dxi = 0; dxi < 3; ++dxi) {
            const int dx = dxi - 1;
            uint32_t aoff[2]; int arow[2];
            #pragma unroll
            for (int mi = 0; mi < 2; ++mi) {
                const int r = (arl[mi] + 1 + dy) * 66 + (axc[mi] + 1 + dx);
                aoff[mi] = (uint32_t)r * 64;
                arow[mi] = r;
            }
            const uint32_t btile = bstage + (uint32_t)(dxi * 2) * B_TILE;

            #pragma unroll
            for (int ks = 0; ks < 2; ++ks) {
                uint32_t ah[2][4], al[2][4], bh[4][4], bl[4][4];
                #pragma unroll
                for (int mi = 0; mi < 2; ++mi) {
                    const uint32_t off = aoff[mi] + SWC(ks * 2 + ca, arow[mi]);
                    ldmx4(ah[mi], abase + off);
                    ldmx4(al[mi], abase + A_PTILE + off);
                }
                #pragma unroll
                for (int nj = 0; nj < 4; ++nj) {
                    const int row = warp_n * 64 + nj * 16 + lb;
                    const uint32_t off = (uint32_t)row * 64 + SWC(ks * 2 + cb, row);
                    ldmx4(bh[nj], btile + off);
                    ldmx4(bl[nj], btile + B_TILE + off);
                }
                #pragma unroll
                for (int mi = 0; mi < 2; ++mi) {
                    #pragma unroll
                    for (int ni = 0; ni < 8; ++ni) {
                        const uint32_t* ph = &bh[ni >> 1][(ni & 1) * 2];
                        const uint32_t* pl = &bl[ni >> 1][(ni & 1) * 2];
                        mma16816(acc[mi][ni], ah[mi], ph);   // hi*hi
                        mma16816(acc[mi][ni], ah[mi], pl);   // hi*lo
                        mma16816(acc[mi][ni], al[mi], ph);   // lo*hi
                    }
                }
            }
        }
    }

    __syncthreads();

    // ---- epilogue: transpose through smem, coalesced float4 stores ----
    float* sC = (float*)dsm;                 // [128 oc][264 px-padded]
    const int r0 = lane >> 2;
    const int col0 = (lane & 3) * 2;
    #pragma unroll
    for (int mi = 0; mi < 2; ++mi) {
        #pragma unroll
        for (int ni = 0; ni < 8; ++ni) {
            const int px = warp_m * 32 + mi * 16 + r0;
            const int oc = warp_n * 64 + ni * 8 + col0;
            sC[oc * 264 + px]           = acc[mi][ni][0];
            sC[(oc + 1) * 264 + px]     = acc[mi][ni][1];
            sC[oc * 264 + px + 8]       = acc[mi][ni][2];
            sC[(oc + 1) * 264 + px + 8] = acc[mi][ni][3];
        }
    }
    __syncthreads();

    #pragma unroll
    for (int it = 0; it < 16; ++it) {
        const int linear = t + it * 512;
        const int oc = linear >> 6;
        const int q = linear & 63;
        float4 v = *(const float4*)&sC[oc * 264 + q * 4];
        const int yy = y0 + (q >> 4);
        const int xx = (q & 15) * 4;
        *(float4*)&out[((size_t)(n * OCC + oc0 + oc) * HH + yy) * WW + xx] = v;
    }
}

// ---------------------------------------------------------------------------
extern "C" void kernel_launch(void* const* d_in, const int* in_sizes, int n_in,
                              void* d_out, int out_size) {
    const float* x  = (const float*)d_in[0];
    const float* z  = (const float*)d_in[1];
    const float* W1 = (const float*)d_in[2];
    const float* B1 = (const float*)d_in[3];
    const float* W2 = (const float*)d_in[4];
    const float* B2 = (const float*)d_in[5];
    float* out = (float*)d_out;

    dim3 tg(64, 32, 2);
    x_convert_kernel<<<tg, 256>>>(x);

    weight_gen_kernel<<<dim3(16, 16), 256>>>(z, W1, B1, W2, B2);

    cudaFuncSetAttribute(conv_mma_kernel,
                         cudaFuncAttributeMaxDynamicSharedMemorySize, SMEM_DYN);
    conv_mma_kernel<<<dim3(16, 32, 2), 512, SMEM_DYN>>>(out);
}

// round 7
// speedup vs baseline: 1.3869x; 1.3869x over previous
#include <cuda_runtime.h>
#include <cuda_bf16.h>
#include <cstdint>

// ===========================================================================
// HyperConvS, tf32 single-pass: x NHWC tf32 convert (channel-interleaved) ->
// weight-gen (tf32, same interleave) -> implicit GEMM conv with
// mma.sync.m16n8k8.tf32, fp32 accum. M=256 x N=128 CTA, 512 threads,
// halo A-tile reused across taps, 24 double-buffered stages.
// ===========================================================================

#define HH 64
#define WW 64
#define CC 256
#define OCC 256

__device__ float g_x[32 * 64 * 64 * 256];   // NHWC, tf32-rounded, ch-interleaved
__device__ float g_w[9 * 256 * 256];        // [tap][oc][ic-interleaved], tf32

// ---- helpers ----
__device__ __forceinline__ uint32_t smem_u32(const void* p) {
    uint32_t a;
    asm("{ .reg .u64 t; cvta.to.shared.u64 t, %1; cvt.u32.u64 %0, t; }"
        : "=r"(a) : "l"(p));
    return a;
}
__device__ __forceinline__ void cp_async16(uint32_t dst, const void* src, uint32_t nbytes) {
    asm volatile("cp.async.cg.shared.global [%0], [%1], 16, %2;"
                 :: "r"(dst), "l"(src), "r"(nbytes) : "memory");
}
__device__ __forceinline__ void cp_commit() {
    asm volatile("cp.async.commit_group;" ::: "memory");
}
template <int N>
__device__ __forceinline__ void cp_wait() {
    asm volatile("cp.async.wait_group %0;" :: "n"(N) : "memory");
}
__device__ __forceinline__ void lds128(uint32_t* r, uint32_t addr) {
    asm volatile("ld.shared.v4.b32 {%0,%1,%2,%3}, [%4];"
                 : "=r"(r[0]), "=r"(r[1]), "=r"(r[2]), "=r"(r[3]) : "r"(addr));
}
__device__ __forceinline__ void mma_tf32(float* c, uint32_t a0, uint32_t a1,
                                         uint32_t a2, uint32_t a3,
                                         uint32_t b0, uint32_t b1) {
    asm volatile(
        "mma.sync.aligned.m16n8k8.row.col.f32.tf32.tf32.f32 "
        "{%0,%1,%2,%3}, {%4,%5,%6,%7}, {%8,%9}, {%0,%1,%2,%3};"
        : "+f"(c[0]), "+f"(c[1]), "+f"(c[2]), "+f"(c[3])
        : "r"(a0), "r"(a1), "r"(a2), "r"(a3), "r"(b0), "r"(b1));
}
__device__ __forceinline__ uint32_t f2tf32(float v) {
    uint32_t o;
    asm("cvt.rna.tf32.f32 %0, %1;" : "=r"(o) : "f"(v));
    return o;
}

// ---------------------------------------------------------------------------
// Kernel: weight generation -> tf32 g_w[tap][oc][ic-interleaved].
// Within each 16-block, channel b is stored at position 4*(b%4) + b/4.
// ---------------------------------------------------------------------------
__global__ __launch_bounds__(256)
void weight_gen_kernel(const float* __restrict__ z,
                       const float* __restrict__ W1,
                       const float* __restrict__ B1,
                       const float* __restrict__ W2,
                       const float* __restrict__ B2) {
    __shared__ float w1t[64 * 65];     // [n][d]
    __shared__ float w2t[64 * 149];    // [d][k]
    __shared__ float z_s[16 * 64];
    __shared__ float a_s[16 * 64];
    const int b  = blockIdx.x;
    const int lg = blockIdx.y;
    const int t  = threadIdx.x;
    const int bpos = ((b & 3) << 2) | (b >> 2);   // interleaved position

    for (int i = t; i < 64 * 64; i += 256) {
        const int d = i >> 6, n = i & 63;
        w1t[n * 65 + d] = W1[(b * 64 + d) * 64 + n];
    }
    for (int i = t; i < 144 * 64; i += 256) {
        const int k = i >> 6, d = i & 63;
        w2t[d * 149 + k] = W2[(b * 144 + k) * 64 + d];
    }
    for (int i = t; i < 1024; i += 256) z_s[i] = z[lg * 16 * 64 + i];
    __syncthreads();

    for (int i = t; i < 1024; i += 256) {
        const int il = i >> 6, d = i & 63;
        float s = B1[b * 64 + d];
        #pragma unroll 16
        for (int n = 0; n < 64; ++n) s += w1t[n * 65 + d] * z_s[il * 64 + n];
        a_s[i] = s;
    }
    __syncthreads();

    for (int i = t; i < 2304; i += 256) {
        const int il = i / 144, k = i - il * 144;
        float s = B2[b * 144 + k];
        #pragma unroll 16
        for (int d = 0; d < 64; ++d) s += w2t[d * 149 + k] * a_s[il * 64 + d];
        const int b2 = k / 9;
        const int tap = k - b2 * 9;
        const int o = lg * 16 + b2;
        const int icpos = il * 16 + bpos;
        g_w[(tap * 256 + o) * 256 + icpos] = __uint_as_float(f2tf32(s));
    }
}

// ---------------------------------------------------------------------------
// Kernel: NCHW fp32 -> NHWC tf32, channel-interleaved. Warp-local 32x32
// transpose tiles. grid (y=64, n=32, pxhalf=2), 256 threads / 8 warps.
// Warp w handles channels [w*32, w*32+32) x pixels [z*32, z*32+32).
// ---------------------------------------------------------------------------
__global__ __launch_bounds__(256)
void x_convert_kernel(const float* __restrict__ x) {
    __shared__ float tile[8][32][36];
    const int y  = blockIdx.x;
    const int n  = blockIdx.y;
    const int px0 = blockIdx.z * 32;
    const int t  = threadIdx.x;
    const int w  = t >> 5;
    const int lane = t & 31;
    const int c0 = w * 32;

    // load: 8 iters, each = 4 channel rows x 32 px, coalesced float4
    #pragma unroll
    for (int cg = 0; cg < 8; ++cg) {
        const int cl = cg * 4 + (lane >> 3);
        const int pl = (lane & 7) * 4;
        float4 v = *(const float4*)(x +
            (((size_t)(n * CC + c0 + cl) * HH + y) * WW) + px0 + pl);
        *(float4*)&tile[w][cl][pl] = v;
    }
    __syncwarp();

    // write: lane covers one 16B output chunk (4 interleaved channels) per px
    #pragma unroll
    for (int it = 0; it < 8; ++it) {
        const int pl = it * 4 + (lane >> 3);
        const int h = lane & 7;            // chunk within 32 ch
        const int blk = h >> 2;            // 16-block
        const int q = h & 3;               // chunk within block
        uint32_t vv[4];
        #pragma unroll
        for (int i = 0; i < 4; ++i)
            vv[i] = f2tf32(tile[w][blk * 16 + q + 4 * i][pl]);
        float* dst = g_x + ((size_t)(n * HH + y) * WW + px0 + pl) * 256
                   + c0 + blk * 16 + q * 4;
        *(uint4*)dst = make_uint4(vv[0], vv[1], vv[2], vv[3]);
    }
}

// ---------------------------------------------------------------------------
// Kernel: implicit-GEMM conv, tf32.
// CTA: 256 px x 128 oc, 512 threads / 16 warps (warp 32x64).
// Stage s (0..23): chunk = s/3 (32 ch), dy = s%3 - 1; dx unrolled inside.
// A: [2 buf][396 halo rows][128 B] (32 ch fp32/row), chunk-alternating buf.
// B: [2 buf][3 dx][128 oc][128 B], stage-alternating buf.
// 16B-chunk XOR swizzle: phys = log ^ ((row&1)<<2)  -> conflict-free LDS.128.
// ---------------------------------------------------------------------------
#define A_BUF_SZ 50688u                // 396 * 128
#define A_REGION (2 * A_BUF_SZ)       // 101376
#define B_TILE  16384u                // 128 oc * 128 B (per dx)
#define B_STAGE (3 * B_TILE)          // 49152
#define B_OFF   A_REGION
#define SMEM_DYN (A_REGION + 2 * B_STAGE)   // 199680

struct Ctx {
    uint32_t sbase;
    int n, y0, oc0;
};

__device__ __forceinline__ void issue_A(const Ctx& c, int chunk, int t) {
    const int c0 = chunk * 32;
    const uint32_t bufo = (chunk & 1) ? A_BUF_SZ : 0u;
    #pragma unroll
    for (int it = 0; it < 7; ++it) {
        const int idx = t + it * 512;              // 0..3167
        if (idx >= 3168) break;
        const int r = idx >> 3;                    // halo row 0..395
        const int cl = idx & 7;                    // logical 16B chunk
        const int hrow = r / 66;
        const int hcol = r - hrow * 66;
        const int gy = c.y0 - 1 + hrow;
        const int gx = hcol - 1;
        const bool valid = ((unsigned)gy < 64u) && ((unsigned)gx < 64u);
        const float* src = valid
            ? g_x + (((size_t)(c.n * HH + gy) * WW + gx) * 256 + c0 + cl * 4)
            : g_x;
        const uint32_t pcl = (uint32_t)(cl ^ ((r & 1) << 2));
        cp_async16(c.sbase + bufo + (uint32_t)r * 128 + pcl * 16,
                   src, valid ? 16u : 0u);
    }
}

__device__ __forceinline__ void issue_B(const Ctx& c, int s, int t) {
    const int chunk = s / 3;
    const int tr = s - chunk * 3;
    const uint32_t bufo = (uint32_t)(s & 1) * B_STAGE;
    #pragma unroll
    for (int it = 0; it < 6; ++it) {
        const int idx = t + it * 512;              // 0..3071
        const int cl = idx & 7;
        const int oc = (idx >> 3) & 127;
        const int dxi = idx >> 10;
        const int tap = tr * 3 + dxi;
        const float* src = g_w +
            ((size_t)(tap * 256 + c.oc0 + oc) * 256 + chunk * 32 + cl * 4);
        const uint32_t pcl = (uint32_t)(cl ^ ((oc & 1) << 2));
        cp_async16(c.sbase + B_OFF + bufo + (uint32_t)dxi * B_TILE
                   + (uint32_t)oc * 128 + pcl * 16, src, 16u);
    }
}

__global__ __launch_bounds__(512, 1)
void conv_mma_kernel(float* __restrict__ out) {
    extern __shared__ char dsm[];
    const uint32_t sbase = smem_u32(dsm);

    const int t = threadIdx.x;
    const int lane = t & 31;
    const int wid = t >> 5;
    const int warp_m = wid & 7;
    const int warp_n = wid >> 3;
    const int y0 = blockIdx.x * 4;
    const int n = blockIdx.y;
    const int oc0 = blockIdx.z * 128;

    Ctx ctx; ctx.sbase = sbase; ctx.n = n; ctx.y0 = y0; ctx.oc0 = oc0;

    float acc[2][8][4];
    #pragma unroll
    for (int mi = 0; mi < 2; ++mi)
        #pragma unroll
        for (int ni = 0; ni < 8; ++ni)
            #pragma unroll
            for (int k = 0; k < 4; ++k) acc[mi][ni][k] = 0.f;

    // fragment coords
    const int frow = lane >> 2;        // 0..7
    const int fcol = lane & 3;         // 0..3

    // per-mi base pixel (m-block start) coordinates
    int mrl[2], mxc[2];
    #pragma unroll
    for (int mi = 0; mi < 2; ++mi) {
        const int m0 = warp_m * 32 + mi * 16;
        mrl[mi] = m0 >> 6;
        mxc[mi] = m0 & 63;
    }

    issue_A(ctx, 0, t);
    issue_B(ctx, 0, t);
    cp_commit();

    for (int s = 0; s < 24; ++s) {
        cp_wait<0>();
        __syncthreads();

        {
            bool did = false;
            if ((s % 3) == 0 && (s / 3) + 1 < 8) { issue_A(ctx, s / 3 + 1, t); did = true; }
            if (s + 1 < 24) { issue_B(ctx, s + 1, t); did = true; }
            if (did) cp_commit();
        }

        const int chunk = s / 3;
        const int dy = (s - chunk * 3) - 1;
        const uint32_t abase = sbase + ((chunk & 1) ? A_BUF_SZ : 0u);
        const uint32_t bstage = sbase + B_OFF + (uint32_t)(s & 1) * B_STAGE;

        #pragma unroll
        for (int dxi = 0; dxi < 3; ++dxi) {
            const int dx = dxi - 1;
            const uint32_t btile = bstage + (uint32_t)dxi * B_TILE;

            // per-mi pixel row for this lane (fragment rows frow, frow+8)
            uint32_t apix[2];
            #pragma unroll
            for (int mi = 0; mi < 2; ++mi)
                apix[mi] = (uint32_t)((mrl[mi] + 1 + dy) * 66
                                      + (mxc[mi] + 1 + dx) + frow);

            #pragma unroll
            for (int k16 = 0; k16 < 2; ++k16) {
                uint32_t a[2][2][4];     // [mi][lo(row r)/hi(row r+8)][4]
                #pragma unroll
                for (int mi = 0; mi < 2; ++mi) {
                    const uint32_t p = apix[mi];
                    const uint32_t pcl = (uint32_t)((k16 * 4 + fcol) ^ ((p & 1) << 2));
                    const uint32_t ad = abase + p * 128 + pcl * 16;
                    lds128(a[mi][0], ad);
                    lds128(a[mi][1], ad + 1024);     // +8 pixels, same parity
                }
                #pragma unroll
                for (int njh = 0; njh < 2; ++njh) {
                    uint32_t bb[4][4];
                    #pragma unroll
                    for (int nj = 0; nj < 4; ++nj) {
                        const uint32_t row = (uint32_t)(warp_n * 64
                                           + (njh * 4 + nj) * 8 + frow);
                        const uint32_t pcl = (uint32_t)((k16 * 4 + fcol) ^ ((row & 1) << 2));
                        lds128(bb[nj], btile + row * 128 + pcl * 16);
                    }
                    #pragma unroll
                    for (int mi = 0; mi < 2; ++mi) {
                        #pragma unroll
                        for (int nj = 0; nj < 4; ++nj) {
                            float* cacc = acc[mi][njh * 4 + nj];
                            mma_tf32(cacc, a[mi][0][0], a[mi][1][0],
                                           a[mi][0][1], a[mi][1][1],
                                           bb[nj][0], bb[nj][1]);
                            mma_tf32(cacc, a[mi][0][2], a[mi][1][2],
                                           a[mi][0][3], a[mi][1][3],
                                           bb[nj][2], bb[nj][3]);
                        }
                    }
                }
            }
        }
    }

    __syncthreads();

    // ---- epilogue: transpose through smem, coalesced float4 stores ----
    float* sC = (float*)dsm;                 // [128 oc][264 px-padded]
    const int r0 = lane >> 2;
    const int col0 = (lane & 3) * 2;
    #pragma unroll
    for (int mi = 0; mi < 2; ++mi) {
        #pragma unroll
        for (int ni = 0; ni < 8; ++ni) {
            const int px = warp_m * 32 + mi * 16 + r0;
            const int oc = warp_n * 64 + ni * 8 + col0;
            sC[oc * 264 + px]           = acc[mi][ni][0];
            sC[(oc + 1) * 264 + px]     = acc[mi][ni][1];
            sC[oc * 264 + px + 8]       = acc[mi][ni][2];
            sC[(oc + 1) * 264 + px + 8] = acc[mi][ni][3];
        }
    }
    __syncthreads();

    #pragma unroll
    for (int it = 0; it < 16; ++it) {
        const int linear = t + it * 512;
        const int oc = linear >> 6;
        const int q = linear & 63;
        float4 v = *(const float4*)&sC[oc * 264 + q * 4];
        const int yy = y0 + (q >> 4);
        const int xx = (q & 15) * 4;
        *(float4*)&out[((size_t)(n * OCC + oc0 + oc) * HH + yy) * WW + xx] = v;
    }
}

// ---------------------------------------------------------------------------
extern "C" void kernel_launch(void* const* d_in, const int* in_sizes, int n_in,
                              void* d_out, int out_size) {
    const float* x  = (const float*)d_in[0];
    const float* z  = (const float*)d_in[1];
    const float* W1 = (const float*)d_in[2];
    const float* B1 = (const float*)d_in[3];
    const float* W2 = (const float*)d_in[4];
    const float* B2 = (const float*)d_in[5];
    float* out = (float*)d_out;

    x_convert_kernel<<<dim3(64, 32, 2), 256>>>(x);

    weight_gen_kernel<<<dim3(16, 16), 256>>>(z, W1, B1, W2, B2);

    cudaFuncSetAttribute(conv_mma_kernel,
                         cudaFuncAttributeMaxDynamicSharedMemorySize, SMEM_DYN);
    conv_mma_kernel<<<dim3(16, 32, 2), 512, SMEM_DYN>>>(out);
}

// round 8
// speedup vs baseline: 1.4866x; 1.0719x over previous
#include <cuda_runtime.h>
#include <cuda_bf16.h>
#include <cstdint>

// ===========================================================================
// HyperConvS, tf32 single-pass: x NHWC tf32 convert (channel-interleaved) ->
// weight-gen (tf32, same interleave) -> implicit GEMM conv with
// mma.sync.m16n8k8.tf32, fp32 accum. CTA 256px x 128oc, 256 threads,
// 8 warps of 64x64 (high fragment reuse), 24 double-buffered stages.
// ===========================================================================

#define HH 64
#define WW 64
#define CC 256
#define OCC 256

__device__ float g_x[32 * 64 * 64 * 256];   // NHWC, tf32-rounded, ch-interleaved
__device__ float g_w[9 * 256 * 256];        // [tap][oc][ic-interleaved], tf32

// ---- helpers ----
__device__ __forceinline__ uint32_t smem_u32(const void* p) {
    uint32_t a;
    asm("{ .reg .u64 t; cvta.to.shared.u64 t, %1; cvt.u32.u64 %0, t; }"
        : "=r"(a) : "l"(p));
    return a;
}
__device__ __forceinline__ void cp_async16(uint32_t dst, const void* src, uint32_t nbytes) {
    asm volatile("cp.async.cg.shared.global [%0], [%1], 16, %2;"
                 :: "r"(dst), "l"(src), "r"(nbytes) : "memory");
}
__device__ __forceinline__ void cp_commit() {
    asm volatile("cp.async.commit_group;" ::: "memory");
}
template <int N>
__device__ __forceinline__ void cp_wait() {
    asm volatile("cp.async.wait_group %0;" :: "n"(N) : "memory");
}
__device__ __forceinline__ void lds128(uint32_t* r, uint32_t addr) {
    asm volatile("ld.shared.v4.b32 {%0,%1,%2,%3}, [%4];"
                 : "=r"(r[0]), "=r"(r[1]), "=r"(r[2]), "=r"(r[3]) : "r"(addr));
}
__device__ __forceinline__ void mma_tf32(float* c, uint32_t a0, uint32_t a1,
                                         uint32_t a2, uint32_t a3,
                                         uint32_t b0, uint32_t b1) {
    asm volatile(
        "mma.sync.aligned.m16n8k8.row.col.f32.tf32.tf32.f32 "
        "{%0,%1,%2,%3}, {%4,%5,%6,%7}, {%8,%9}, {%0,%1,%2,%3};"
        : "+f"(c[0]), "+f"(c[1]), "+f"(c[2]), "+f"(c[3])
        : "r"(a0), "r"(a1), "r"(a2), "r"(a3), "r"(b0), "r"(b1));
}
__device__ __forceinline__ uint32_t f2tf32(float v) {
    uint32_t o;
    asm("cvt.rna.tf32.f32 %0, %1;" : "=r"(o) : "f"(v));
    return o;
}

// ---------------------------------------------------------------------------
// Kernel: weight generation -> tf32 g_w[tap][oc][ic-interleaved].
// ---------------------------------------------------------------------------
__global__ __launch_bounds__(256)
void weight_gen_kernel(const float* __restrict__ z,
                       const float* __restrict__ W1,
                       const float* __restrict__ B1,
                       const float* __restrict__ W2,
                       const float* __restrict__ B2) {
    __shared__ float w1t[64 * 65];     // [n][d]
    __shared__ float w2t[64 * 149];    // [d][k]
    __shared__ float z_s[16 * 64];
    __shared__ float a_s[16 * 64];
    const int b  = blockIdx.x;
    const int lg = blockIdx.y;
    const int t  = threadIdx.x;
    const int bpos = ((b & 3) << 2) | (b >> 2);   // interleaved position

    for (int i = t; i < 64 * 64; i += 256) {
        const int d = i >> 6, n = i & 63;
        w1t[n * 65 + d] = W1[(b * 64 + d) * 64 + n];
    }
    for (int i = t; i < 144 * 64; i += 256) {
        const int k = i >> 6, d = i & 63;
        w2t[d * 149 + k] = W2[(b * 144 + k) * 64 + d];
    }
    for (int i = t; i < 1024; i += 256) z_s[i] = z[lg * 16 * 64 + i];
    __syncthreads();

    for (int i = t; i < 1024; i += 256) {
        const int il = i >> 6, d = i & 63;
        float s = B1[b * 64 + d];
        #pragma unroll 16
        for (int n = 0; n < 64; ++n) s += w1t[n * 65 + d] * z_s[il * 64 + n];
        a_s[i] = s;
    }
    __syncthreads();

    for (int i = t; i < 2304; i += 256) {
        const int il = i / 144, k = i - il * 144;
        float s = B2[b * 144 + k];
        #pragma unroll 16
        for (int d = 0; d < 64; ++d) s += w2t[d * 149 + k] * a_s[il * 64 + d];
        const int b2 = k / 9;
        const int tap = k - b2 * 9;
        const int o = lg * 16 + b2;
        const int icpos = il * 16 + bpos;
        g_w[(tap * 256 + o) * 256 + icpos] = __uint_as_float(f2tf32(s));
    }
}

// ---------------------------------------------------------------------------
// Kernel: NCHW fp32 -> NHWC tf32, channel-interleaved.
// ---------------------------------------------------------------------------
__global__ __launch_bounds__(256)
void x_convert_kernel(const float* __restrict__ x) {
    __shared__ float tile[8][32][36];
    const int y  = blockIdx.x;
    const int n  = blockIdx.y;
    const int px0 = blockIdx.z * 32;
    const int t  = threadIdx.x;
    const int w  = t >> 5;
    const int lane = t & 31;
    const int c0 = w * 32;

    #pragma unroll
    for (int cg = 0; cg < 8; ++cg) {
        const int cl = cg * 4 + (lane >> 3);
        const int pl = (lane & 7) * 4;
        float4 v = *(const float4*)(x +
            (((size_t)(n * CC + c0 + cl) * HH + y) * WW) + px0 + pl);
        *(float4*)&tile[w][cl][pl] = v;
    }
    __syncwarp();

    #pragma unroll
    for (int it = 0; it < 8; ++it) {
        const int pl = it * 4 + (lane >> 3);
        const int h = lane & 7;
        const int blk = h >> 2;
        const int q = h & 3;
        uint32_t vv[4];
        #pragma unroll
        for (int i = 0; i < 4; ++i)
            vv[i] = f2tf32(tile[w][blk * 16 + q + 4 * i][pl]);
        float* dst = g_x + ((size_t)(n * HH + y) * WW + px0 + pl) * 256
                   + c0 + blk * 16 + q * 4;
        *(uint4*)dst = make_uint4(vv[0], vv[1], vv[2], vv[3]);
    }
}

// ---------------------------------------------------------------------------
// Kernel: implicit-GEMM conv, tf32, 8 warps of 64x64.
// CTA: 256 px (4 rows x 64 cols) x 128 oc, 256 threads.
// warp_m = wid&3 (image row), warp_n = wid>>2. Warp tile: row warp_m,
// columns [mi*16, mi*16+16) for mi=0..3, oc [warp_n*64, +64).
// Stage s (0..23): chunk = s/3 (32 ch), dy = s%3 - 1; dx unrolled inside.
// A: [2 buf][396 halo rows][128 B]; B: [2 buf][3 dx][128 oc][128 B].
// ---------------------------------------------------------------------------
#define A_BUF_SZ 50688u                // 396 * 128
#define A_REGION (2 * A_BUF_SZ)       // 101376
#define B_TILE  16384u                // 128 oc * 128 B (per dx)
#define B_STAGE (3 * B_TILE)          // 49152
#define B_OFF   A_REGION
#define SMEM_DYN (A_REGION + 2 * B_STAGE)   // 199680

struct Ctx {
    uint32_t sbase;
    int n, y0, oc0;
};

__device__ __forceinline__ void issue_A(const Ctx& c, int chunk, int t) {
    const int c0 = chunk * 32;
    const uint32_t bufo = (chunk & 1) ? A_BUF_SZ : 0u;
    #pragma unroll
    for (int it = 0; it < 13; ++it) {
        const int idx = t + it * 256;              // 0..3167
        if (idx >= 3168) break;
        const int r = idx >> 3;                    // halo row 0..395
        const int cl = idx & 7;                    // logical 16B chunk
        const int hrow = r / 66;
        const int hcol = r - hrow * 66;
        const int gy = c.y0 - 1 + hrow;
        const int gx = hcol - 1;
        const bool valid = ((unsigned)gy < 64u) && ((unsigned)gx < 64u);
        const float* src = valid
            ? g_x + (((size_t)(c.n * HH + gy) * WW + gx) * 256 + c0 + cl * 4)
            : g_x;
        const uint32_t pcl = (uint32_t)(cl ^ ((r & 1) << 2));
        cp_async16(c.sbase + bufo + (uint32_t)r * 128 + pcl * 16,
                   src, valid ? 16u : 0u);
    }
}

__device__ __forceinline__ void issue_B(const Ctx& c, int s, int t) {
    const int chunk = s / 3;
    const int tr = s - chunk * 3;
    const uint32_t bufo = (uint32_t)(s & 1) * B_STAGE;
    #pragma unroll
    for (int it = 0; it < 12; ++it) {
        const int idx = t + it * 256;              // 0..3071
        const int cl = idx & 7;
        const int oc = (idx >> 3) & 127;
        const int dxi = idx >> 10;
        const int tap = tr * 3 + dxi;
        const float* src = g_w +
            ((size_t)(tap * 256 + c.oc0 + oc) * 256 + chunk * 32 + cl * 4);
        const uint32_t pcl = (uint32_t)(cl ^ ((oc & 1) << 2));
        cp_async16(c.sbase + B_OFF + bufo + (uint32_t)dxi * B_TILE
                   + (uint32_t)oc * 128 + pcl * 16, src, 16u);
    }
}

__global__ __launch_bounds__(256, 1)
void conv_mma_kernel(float* __restrict__ out) {
    extern __shared__ char dsm[];
    const uint32_t sbase = smem_u32(dsm);

    const int t = threadIdx.x;
    const int lane = t & 31;
    const int wid = t >> 5;
    const int warp_m = wid & 3;        // image row within CTA tile
    const int warp_n = wid >> 2;       // oc half
    const int y0 = blockIdx.x * 4;
    const int n = blockIdx.y;
    const int oc0 = blockIdx.z * 128;

    Ctx ctx; ctx.sbase = sbase; ctx.n = n; ctx.y0 = y0; ctx.oc0 = oc0;

    float acc[4][8][4];
    #pragma unroll
    for (int mi = 0; mi < 4; ++mi)
        #pragma unroll
        for (int ni = 0; ni < 8; ++ni)
            #pragma unroll
            for (int k = 0; k < 4; ++k) acc[mi][ni][k] = 0.f;

    const int frow = lane >> 2;        // 0..7
    const int fcol = lane & 3;         // 0..3

    issue_A(ctx, 0, t);
    issue_B(ctx, 0, t);
    cp_commit();

    for (int s = 0; s < 24; ++s) {
        cp_wait<0>();
        __syncthreads();

        {
            bool did = false;
            if ((s % 3) == 0 && (s / 3) + 1 < 8) { issue_A(ctx, s / 3 + 1, t); did = true; }
            if (s + 1 < 24) { issue_B(ctx, s + 1, t); did = true; }
            if (did) cp_commit();
        }

        const int chunk = s / 3;
        const int dy = (s - chunk * 3) - 1;
        const uint32_t abase = sbase + ((chunk & 1) ? A_BUF_SZ : 0u);
        const uint32_t bstage = sbase + B_OFF + (uint32_t)(s & 1) * B_STAGE;

        // halo row base for this warp's image row + dy
        const int hrow_base = (warp_m + 1 + dy) * 66;

        #pragma unroll
        for (int dxi = 0; dxi < 3; ++dxi) {
            const int dx = dxi - 1;
            const uint32_t btile = bstage + (uint32_t)dxi * B_TILE;

            #pragma unroll
            for (int k16 = 0; k16 < 2; ++k16) {
                uint32_t a[4][2][4];   // [mi][px +0 / +8][4]
                #pragma unroll
                for (int mi = 0; mi < 4; ++mi) {
                    const uint32_t p = (uint32_t)(hrow_base + mi * 16 + 1 + dx + frow);
                    const uint32_t pcl = (uint32_t)((k16 * 4 + fcol) ^ ((p & 1) << 2));
                    const uint32_t ad = abase + p * 128 + pcl * 16;
                    lds128(a[mi][0], ad);
                    lds128(a[mi][1], ad + 1024);     // +8 pixels, same parity
                }
                uint32_t bb[8][4];
                #pragma unroll
                for (int nj = 0; nj < 8; ++nj) {
                    const uint32_t row = (uint32_t)(warp_n * 64 + nj * 8 + frow);
                    const uint32_t pcl = (uint32_t)((k16 * 4 + fcol) ^ ((row & 1) << 2));
                    lds128(bb[nj], btile + row * 128 + pcl * 16);
                }
                #pragma unroll
                for (int mi = 0; mi < 4; ++mi) {
                    #pragma unroll
                    for (int nj = 0; nj < 8; ++nj) {
                        float* cacc = acc[mi][nj];
                        mma_tf32(cacc, a[mi][0][0], a[mi][1][0],
                                       a[mi][0][1], a[mi][1][1],
                                       bb[nj][0], bb[nj][1]);
                        mma_tf32(cacc, a[mi][0][2], a[mi][1][2],
                                       a[mi][0][3], a[mi][1][3],
                                       bb[nj][2], bb[nj][3]);
                    }
                }
            }
        }
    }

    __syncthreads();

    // ---- epilogue: transpose through smem, coalesced float4 stores ----
    float* sC = (float*)dsm;                 // [128 oc][264 px-padded]
    const int r0 = lane >> 2;
    const int col0 = (lane & 3) * 2;
    #pragma unroll
    for (int mi = 0; mi < 4; ++mi) {
        #pragma unroll
        for (int ni = 0; ni < 8; ++ni) {
            const int px = warp_m * 64 + mi * 16 + r0;
            const int oc = warp_n * 64 + ni * 8 + col0;
            sC[oc * 264 + px]           = acc[mi][ni][0];
            sC[(oc + 1) * 264 + px]     = acc[mi][ni][1];
            sC[oc * 264 + px + 8]       = acc[mi][ni][2];
            sC[(oc + 1) * 264 + px + 8] = acc[mi][ni][3];
        }
    }
    __syncthreads();

    #pragma unroll
    for (int it = 0; it < 32; ++it) {
        const int linear = t + it * 256;
        const int oc = linear >> 6;
        const int q = linear & 63;
        float4 v = *(const float4*)&sC[oc * 264 + q * 4];
        const int yy = y0 + (q >> 4);
        const int xx = (q & 15) * 4;
        *(float4*)&out[((size_t)(n * OCC + oc0 + oc) * HH + yy) * WW + xx] = v;
    }
}

// ---------------------------------------------------------------------------
extern "C" void kernel_launch(void* const* d_in, const int* in_sizes, int n_in,
                              void* d_out, int out_size) {
    const float* x  = (const float*)d_in[0];
    const float* z  = (const float*)d_in[1];
    const float* W1 = (const float*)d_in[2];
    const float* B1 = (const float*)d_in[3];
    const float* W2 = (const float*)d_in[4];
    const float* B2 = (const float*)d_in[5];
    float* out = (float*)d_out;

    x_convert_kernel<<<dim3(64, 32, 2), 256>>>(x);

    weight_gen_kernel<<<dim3(16, 16), 256>>>(z, W1, B1, W2, B2);

    cudaFuncSetAttribute(conv_mma_kernel,
                         cudaFuncAttributeMaxDynamicSharedMemorySize, SMEM_DYN);
    conv_mma_kernel<<<dim3(16, 32, 2), 256, SMEM_DYN>>>(out);
}